// round 10
// baseline (speedup 1.0000x reference)
#include <cuda_runtime.h>
#include <cuda_bf16.h>
#include <math.h>
#include <stdint.h>

#define NB   12000
#define NBP  12032   // NB padded to 94*128
#define Dd   64
#define Bb   1024
#define Ll   20
#define BKk  10
#define NOLDn 20

// ---------------- scratch (device globals; no allocation allowed) ----------
__device__ float g_baskets[4 * Bb * Ll * Dd];
__device__ float g_s1[4 * Bb * Dd];
__device__ float g_s2[4 * Bb * Dd];
__device__ float g_s3[4 * Bb * Dd];
__device__ float g_lvec[4 * Bb * Dd];
__device__ float g_feach[4 * Bb * Dd];
__device__ float g_Afin[Bb * 128];              // [final | e_user]
__device__ float g_uwT[NBP * 64];               // u_w transposed: [e][k]
__device__ uint4 g_Sq[NBP * 16];                // e_all bf16 hi/lo fragments
__device__ uint4 g_Uq[NBP * 16];                // uwT fragments
__device__ uint4 g_Aq[2 * Bb * 16];             // Afin fragments (2 halves)

__device__ __forceinline__ float sigmoidf(float x) { return 1.f / (1.f + expf(-x)); }

// ===================== bf16x2 (split-2) mma.sync GEMM =======================
__device__ __forceinline__ void mma16(float* d, const uint32_t* a, const uint32_t* b) {
    asm volatile(
        "mma.sync.aligned.m16n8k16.row.col.f32.bf16.bf16.f32 "
        "{%0,%1,%2,%3}, {%4,%5,%6,%7}, {%8,%9}, {%0,%1,%2,%3};"
        : "+f"(d[0]), "+f"(d[1]), "+f"(d[2]), "+f"(d[3])
        : "r"(a[0]), "r"(a[1]), "r"(a[2]), "r"(a[3]), "r"(b[0]), "r"(b[1]));
}

__device__ __forceinline__ uint32_t packbf(__nv_bfloat16 lo, __nv_bfloat16 hi) {
    __nv_bfloat162 t = __halves2bfloat162(lo, hi);
    return *(uint32_t*)&t;
}

__device__ __forceinline__ void splitpair(float x, float y, uint32_t& hi, uint32_t& lo) {
    __nv_bfloat16 hx = __float2bfloat16_rn(x), hy = __float2bfloat16_rn(y);
    __nv_bfloat16 lx = __float2bfloat16_rn(x - __bfloat162float(hx));
    __nv_bfloat16 ly = __float2bfloat16_rn(y - __bfloat162float(hy));
    hi = packbf(hx, hy);
    lo = packbf(lx, ly);
}

// ---- prep: split a row-major fp32 matrix into fragment-layout uint4 array --
// dst[row*16 + s*4 + t] = {hi(k0,k0+1), hi(k0+8,k0+9), lo(k0,k0+1), lo(k0+8,k0+9)}
// with s = k16-block (0..3), t = k-pair-in-8 (0..3), k0 = s*16 + 2t.
// Rows >= srows are zero-filled (padding).
__global__ void k_prep(const float* __restrict__ src, long srows, int stride,
                       uint4* __restrict__ dst, long drows) {
    long gid = (long)blockIdx.x * blockDim.x + threadIdx.x;
    if (gid >= drows * 2) return;
    long row = gid >> 1;
    int h = (int)(gid & 1);          // k half: 0 -> k 0..31, 1 -> 32..63
    float f[32];
    if (row < srows) {
        const float* base = src + row * (long)stride + h * 32;
#pragma unroll
        for (int i = 0; i < 8; i++) *(float4*)&f[i * 4] = *(const float4*)&base[i * 4];
    } else {
#pragma unroll
        for (int i = 0; i < 32; i++) f[i] = 0.f;
    }
    uint4* d = dst + row * 16;
#pragma unroll
    for (int sb = 0; sb < 2; sb++) {
#pragma unroll
        for (int t = 0; t < 4; t++) {
            int k0 = sb * 16 + 2 * t;
            uint4 v;
            splitpair(f[k0], f[k0 + 1], v.x, v.z);
            splitpair(f[k0 + 8], f[k0 + 9], v.y, v.w);
            d[(2 * h + sb) * 4 + t] = v;
        }
    }
}

// Generic tile GEMM on pre-split fragment arrays.
// C[i][j] = sum_h sum_k A_h[i][k] * B_h[j][k] (+ bias[j]); tiles 128x128.
// triangular=1: linear upper-triangle tile id; mirrored for off-diagonal.
__global__ void __launch_bounds__(256, 2)
k_mma(const uint4* __restrict__ A1q, const uint4* __restrict__ A2q,
      const uint4* __restrict__ B1q, const uint4* __restrict__ B2q,
      long a_rows, long b_rows, float* __restrict__ C,
      const float* __restrict__ bias, int triangular)
{
    extern __shared__ float st[];    // 128*133 floats mirror staging

    int tid = threadIdx.x;
    int bi, bj;
    if (triangular) {
        int lid = blockIdx.x;
        int r = (int)((sqrtf(8.f * (float)lid + 1.f) - 1.f) * 0.5f);
        while ((r + 1) * (r + 2) / 2 <= lid) r++;
        while (r * (r + 1) / 2 > lid) r--;
        bi = lid - r * (r + 1) / 2;
        bj = r;
    } else {
        bi = blockIdx.y; bj = blockIdx.x;
    }
    long i0 = (long)bi * 128, j0 = (long)bj * 128;

    int lane = tid & 31, wid = tid >> 5;
    int g = lane >> 2, tig = lane & 3;
    int wm = wid & 3, wn = wid >> 2;   // 4x2 warp grid -> 32x64 per warp

    float acc[2][8][4];
#pragma unroll
    for (int mt = 0; mt < 2; mt++)
#pragma unroll
        for (int nt = 0; nt < 8; nt++)
#pragma unroll
            for (int q = 0; q < 4; q++) acc[mt][nt][q] = 0.f;

    // 32-bit fragment-index bases (fragment arrays < 2^21 entries)
    int arow0 = (int)i0 + wm * 32 + g;
    int bcol0 = (int)j0 + wn * 64 + g;

    int halves = (A2q != nullptr) ? 2 : 1;
    for (int h = 0; h < halves; h++) {
        const uint4* __restrict__ Aq = h ? A2q : A1q;
        const uint4* __restrict__ Bq = h ? B2q : B1q;
        const uint4* ap[2][2];
        const uint4* bp[8];
#pragma unroll
        for (int mt = 0; mt < 2; mt++) {
            int r0 = (arow0 + mt * 16) * 16 + tig;
            ap[mt][0] = Aq + r0;
            ap[mt][1] = Aq + r0 + 8 * 16;
        }
#pragma unroll
        for (int nt = 0; nt < 8; nt++)
            bp[nt] = Bq + (bcol0 + nt * 8) * 16 + tig;

#pragma unroll
        for (int s = 0; s < 4; s++) {
            uint32_t am[2][4], al[2][4];
#pragma unroll
            for (int mt = 0; mt < 2; mt++) {
                uint4 u0 = ap[mt][0][s * 4];
                uint4 u1 = ap[mt][1][s * 4];
                am[mt][0] = u0.x; am[mt][1] = u1.x; am[mt][2] = u0.y; am[mt][3] = u1.y;
                al[mt][0] = u0.z; al[mt][1] = u1.z; al[mt][2] = u0.w; al[mt][3] = u1.w;
            }
#pragma unroll
            for (int nt = 0; nt < 8; nt++) {
                uint4 u = bp[nt][s * 4];
                uint32_t bm[2] = { u.x, u.y };
                uint32_t bl[2] = { u.z, u.w };
#pragma unroll
                for (int mt = 0; mt < 2; mt++) {
                    float* a = acc[mt][nt];
                    mma16(a, am[mt], bm);
                    mma16(a, am[mt], bl);
                    mma16(a, al[mt], bm);
                }
            }
        }
    }

    // ------------- direct stores straight from accumulators (STG.64) --------
    {
        int coloff = (int)j0 + wn * 64 + 2 * tig;
#pragma unroll
        for (int mt = 0; mt < 2; mt++) {
#pragma unroll
            for (int rr = 0; rr < 2; rr++) {
                long gi = i0 + wm * 32 + mt * 16 + rr * 8 + g;
                if (gi < a_rows) {
                    float* rp = C + gi * (long)NB + coloff;
#pragma unroll
                    for (int nt = 0; nt < 8; nt++) {
                        int jc = coloff + nt * 8;
                        if (jc < b_rows) {
                            float2 v;
                            v.x = acc[mt][nt][rr * 2 + 0];
                            v.y = acc[mt][nt][rr * 2 + 1];
                            if (bias) {
                                v.x += __ldg(&bias[jc]);
                                v.y += __ldg(&bias[jc + 1]);
                            }
                            *(float2*)(rp + nt * 8) = v;
                        }
                    }
                }
            }
        }
    }

    // ------------- mirror pass for off-diagonal triangular tiles ------------
    if (triangular && bi != bj) {
#pragma unroll
        for (int mt = 0; mt < 2; mt++)
#pragma unroll
            for (int nt = 0; nt < 8; nt++) {
                int R  = wm * 32 + mt * 16 + g;
                int Cc = wn * 64 + nt * 8 + 2 * tig;
                st[R * 133 + Cc]           = acc[mt][nt][0];
                st[R * 133 + Cc + 1]       = acc[mt][nt][1];
                st[(R + 8) * 133 + Cc]     = acc[mt][nt][2];
                st[(R + 8) * 133 + Cc + 1] = acc[mt][nt][3];
            }
        __syncthreads();
        int ii = tid & 127, jb = tid >> 7;
        long gi = i0 + ii;
        if (gi < a_rows) {
#pragma unroll 8
            for (int q = 0; q < 64; q++) {
                int jj = jb + 2 * q;
                long gj = j0 + jj;
                // C[gj][gi] = tile[ii][jj]
                if (gj < b_rows)
                    C[gj * (long)NB + gi] = st[ii * 133 + jj];
            }
        }
    }
}

// ---------------- u_w transpose: g_uwT[e][k] = u_w[k][e] --------------------
__global__ void __launch_bounds__(1024)
k_uwT(const float* __restrict__ u_w) {
    __shared__ float t[32][33];
    int e0 = blockIdx.x * 32, k0 = blockIdx.y * 32;
    int tx = threadIdx.x & 31, ty = threadIdx.x >> 5;
    t[ty][tx] = u_w[(long)(k0 + ty) * NB + e0 + tx];
    __syncthreads();
    g_uwT[(long)(e0 + ty) * 64 + k0 + tx] = t[tx][ty];
}

// 64-thread block reduction (broadcast result to all threads)
__device__ __forceinline__ float block64_reduce(float v, float* sbuf, int d) {
    sbuf[d] = v;
    __syncthreads();
    if (d < 32) {
        float r = sbuf[d] + sbuf[d + 32];
#pragma unroll
        for (int o = 16; o > 0; o >>= 1) r += __shfl_down_sync(0xffffffffu, r, o);
        if (d == 0) sbuf[0] = r;
    }
    __syncthreads();
    float r = sbuf[0];
    __syncthreads();
    return r;
}

// ---------------- kernel A: baskets gather-sum ------------------------------
__global__ void k_baskets(const int* __restrict__ click, const int* __restrict__ favor,
                          const int* __restrict__ cart, const int* __restrict__ buy,
                          const float* __restrict__ item_emb) {
    int t = threadIdx.x;
    int d = t & 63;
    int row = blockIdx.x * 4 + (t >> 6);
    int n = row / (Bb * Ll);
    int rem = row - n * (Bb * Ll);
    const int* idx;
    if (n == 0) idx = click; else if (n == 1) idx = favor;
    else if (n == 2) idx = cart; else idx = buy;
    idx += rem * BKk;
    float s = 0.f;
#pragma unroll
    for (int k = 0; k < BKk; k++) s += item_emb[idx[k] * Dd + d];
    g_baskets[row * Dd + d] = s;
}

// ---------------- kernel B: per-(n,b) attention + EMA + gate ----------------
__global__ void __launch_bounds__(64)
k_seq(const int* __restrict__ userData, const float* __restrict__ user_emb,
      const float* __restrict__ user_wd, const float* __restrict__ Wk,
      const float* __restrict__ bk, const float* __restrict__ gate_w,
      const float* __restrict__ gate_b, const float* __restrict__ alpha) {
    int nb = blockIdx.x;
    int n = nb / Bb, b = nb - n * Bb;
    int d = threadIdx.x;

    __shared__ float sb[Ll][Dd];
    __shared__ float sred[Dd];
    __shared__ float s_attn[Ll];

    const float* bas = g_baskets + (size_t)nb * Ll * Dd;
#pragma unroll
    for (int l = 0; l < Ll; l++) sb[l][d] = bas[l * Dd + d];

    float wkreg[Dd];
#pragma unroll
    for (int e = 0; e < Dd; e++) wkreg[e] = Wk[n * Dd * Dd + e * Dd + d];

    int u = userData[b];
    float eu = user_emb[u * Dd + d];
    float bkd = bk[n * Dd + d];
    __syncthreads();

    for (int l = 0; l < Ll; l++) {
        float kd = bkd;
#pragma unroll
        for (int e = 0; e < Dd; e++) kd += sb[l][e] * wkreg[e];
        kd = fmaxf(kd, 0.f);
        float sc = block64_reduce(eu * kd, sred, d);
        float rs = block64_reduce(sb[l][d], sred, d);
        if (d == 0) s_attn[l] = (rs != 0.f) ? sc * 0.125f : -1000000000.0f;
        __syncthreads();
    }

    float m = -3.4e38f;
#pragma unroll
    for (int l = 0; l < Ll; l++) m = fmaxf(m, s_attn[l]);
    float ex[Ll];
    float Z = 0.f;
#pragma unroll
    for (int l = 0; l < Ll; l++) { ex[l] = expf(s_attn[l] - m); Z += ex[l]; }
    float invZ = 1.f / Z;
    float lv = 0.f;
#pragma unroll
    for (int l = 0; l < Ll; l++) lv += ex[l] * invZ * sb[l][d];

    float w1 = sigmoidf(user_wd[u * 8 + 2 * n]);
    float w2 = sigmoidf(user_wd[u * 8 + 2 * n + 1]);
    float coef = 1.f - w2 * w1;
    float h1 = sb[0][d];
#pragma unroll
    for (int l = 1; l < Ll; l++) h1 = w1 * h1 + coef * sb[l][d];
    float h2 = sb[Ll / 2][d];
#pragma unroll
    for (int l = Ll / 2 + 1; l < Ll; l++) h2 = w1 * h2 + coef * sb[l][d];
    float h3 = w1 * sb[Ll - 2][d] + coef * sb[Ll - 1][d];

    float a0 = alpha[0], a1 = alpha[1];
    float fn = h1 + a0 * (h1 - h2) + a1 * (h1 - h3);

    float gsum = block64_reduce(fn * gate_w[d] + lv * gate_w[Dd + d], sred, d);
    float g = sigmoidf(gsum + gate_b[0]);
    float fe = g * fn + (1.f - g) * lv;

    int off = nb * Dd + d;
    g_s1[off] = h1; g_s2[off] = h2; g_s3[off] = h3;
    g_lvec[off] = lv; g_feach[off] = fe;
}

// ---------------- kernel C: mixture over behaviors --------------------------
__global__ void __launch_bounds__(64)
k_mix(const int* __restrict__ userData, const float* __restrict__ user_emb,
      const float* __restrict__ w_mix, const float* __restrict__ alpha,
      const float* __restrict__ gate_w, const float* __restrict__ gate_b) {
    int b = blockIdx.x;
    int d = threadIdx.x;
    __shared__ float sred[Dd];

    float w[4][4];
#pragma unroll
    for (int i = 0; i < 4; i++) {
        float mx = -3.4e38f;
#pragma unroll
        for (int j = 0; j < 4; j++) mx = fmaxf(mx, w_mix[i * 4 + j]);
        float Z = 0.f;
#pragma unroll
        for (int j = 0; j < 4; j++) { w[i][j] = expf(w_mix[i * 4 + j] - mx); Z += w[i][j]; }
        float inv = 1.f / Z;
#pragma unroll
        for (int j = 0; j < 4; j++) w[i][j] *= inv;
    }

    float s1m = 0.f, s2m = 0.f, s3m = 0.f, lm = 0.f;
#pragma unroll
    for (int n = 0; n < 4; n++) {
        int off = (n * Bb + b) * Dd + d;
        s1m += w[0][n] * g_s1[off];
        s2m += w[1][n] * g_s2[off];
        s3m += w[2][n] * g_s3[off];
        lm  += w[3][n] * g_lvec[off];
    }
    float a0 = alpha[0], a1 = alpha[1];
    float fin_ = s1m + a0 * (s1m - s2m) + a1 * (s1m - s3m);

    float gsum = block64_reduce(fin_ * gate_w[d] + lm * gate_w[Dd + d], sred, d);
    float gm = sigmoidf(gsum + gate_b[0]);
    float fin = gm * fin_ + (1.f - gm) * lm;

    g_Afin[b * 128 + d] = fin;
    g_Afin[b * 128 + Dd + d] = user_emb[userData[b] * Dd + d];
}

// ---------------- kernel G: sparse old-items corrections --------------------
__global__ void __launch_bounds__(128)
k_sparse(const int* __restrict__ oldItems, const float* __restrict__ item_emb,
         float* __restrict__ out) {
    int b = blockIdx.x;
    int t = threadIdx.x;
    int n = t >> 5, lane = t & 31;
    __shared__ int sh_old[4][NOLDn];
    __shared__ float sh_fin[Dd];
    if (t < Dd) sh_fin[t] = g_Afin[b * 128 + t];
    if (t < 4 * NOLDn) {
        int n2 = t / NOLDn, j = t - n2 * NOLDn;
        sh_old[n2][j] = oldItems[(n2 * Bb + b) * NOLDn + j];
    }
    __syncthreads();

    int d0 = lane, d1 = lane + 32;
    float diff0 = g_feach[(n * Bb + b) * Dd + d0] - sh_fin[d0];
    float diff1 = g_feach[(n * Bb + b) * Dd + d1] - sh_fin[d1];
    const float* eall = item_emb + Dd;

    for (int j = 0; j < NOLDn; j++) {
        int e = sh_old[n][j];
        bool dup = false;
        for (int j2 = 0; j2 < j; j2++) if (sh_old[n][j2] == e) dup = true;
        if (dup) continue;
        float v = diff0 * eall[e * Dd + d0] + diff1 * eall[e * Dd + d1];
#pragma unroll
        for (int o = 16; o > 0; o >>= 1) v += __shfl_down_sync(0xffffffffu, v, o);
        if (lane == 0) atomicAdd(&out[(size_t)b * NB + e], v);
    }
}

// ---------------- kernel F: omiga copy ---------------------------------------
__global__ void k_omiga(const float* __restrict__ omiga, float* __restrict__ out) {
    int i = blockIdx.x * blockDim.x + threadIdx.x;
    if (i < NB) out[i] = omiga[i + 1];
}

// ---------------- launch ------------------------------------------------------
extern "C" void kernel_launch(void* const* d_in, const int* in_sizes, int n_in,
                              void* d_out, int out_size) {
    const int* click = (const int*)d_in[0];
    const int* favor = (const int*)d_in[1];
    const int* cart  = (const int*)d_in[2];
    const int* buy   = (const int*)d_in[3];
    const int* user  = (const int*)d_in[4];
    const int* olds  = (const int*)d_in[5];
    const float* item_emb = (const float*)d_in[6];
    const float* user_emb = (const float*)d_in[7];
    const float* user_wd  = (const float*)d_in[8];
    const float* omiga    = (const float*)d_in[9];
    const float* w_mix    = (const float*)d_in[10];
    const float* alpha    = (const float*)d_in[11];
    const float* gate_w   = (const float*)d_in[12];
    const float* gate_b   = (const float*)d_in[13];
    const float* Wk       = (const float*)d_in[14];
    const float* bk       = (const float*)d_in[15];
    const float* u_w      = (const float*)d_in[16];
    const float* u_b      = (const float*)d_in[17];
    float* out = (float*)d_out;

    const int MMA_SMEM = 128 * 133 * 4;   // 68096 B mirror staging
    cudaFuncSetAttribute(k_mma, cudaFuncAttributeMaxDynamicSharedMemorySize, MMA_SMEM);

    float *p_Afin, *p_uwT;
    uint4 *p_Sq, *p_Uq, *p_Aq;
    cudaGetSymbolAddress((void**)&p_Afin, g_Afin);
    cudaGetSymbolAddress((void**)&p_uwT,  g_uwT);
    cudaGetSymbolAddress((void**)&p_Sq,   g_Sq);
    cudaGetSymbolAddress((void**)&p_Uq,   g_Uq);
    cudaGetSymbolAddress((void**)&p_Aq,   g_Aq);

    const float* e_all = item_emb + Dd;   // rows 1..12000

    // 1: split e_all into fragment layout (NBP rows, zero pad)
    k_prep<<<(NBP * 2 + 255) / 256, 256>>>(e_all, (long)NB, 64, p_Sq, (long)NBP);
    k_baskets<<<4 * Bb * Ll / 4, 256>>>(click, favor, cart, buy, item_emb);
    k_seq<<<4 * Bb, 64>>>(user, user_emb, user_wd, Wk, bk, gate_w, gate_b, alpha);

    // 4: sim = e_all @ e_all^T (triangular + mirror)  [profiled launch]
    {
        int nbT = NBP / 128;                  // 94
        k_mma<<<nbT * (nbT + 1) / 2, 256, MMA_SMEM>>>(p_Sq, nullptr, p_Sq, nullptr,
                                                      (long)NB, (long)NB,
                                                      out + (size_t)Bb * NB, nullptr, 1);
    }

    k_mix<<<Bb, 64>>>(user, user_emb, w_mix, alpha, gate_w, gate_b);
    k_uwT<<<dim3(NB / 32, 2), 1024>>>(u_w);
    k_prep<<<(NBP * 2 + 255) / 256, 256>>>(p_uwT, (long)NB, 64, p_Uq, (long)NBP);
    k_prep<<<(Bb * 2 + 255) / 256, 256>>>(p_Afin, (long)Bb, 128, p_Aq, (long)Bb);
    k_prep<<<(Bb * 2 + 255) / 256, 256>>>(p_Afin + 64, (long)Bb, 128, p_Aq + Bb * 16, (long)Bb);

    // score = [final|e_user] @ [e_all^T ; u_w] + u_b  (two K=64 halves)
    {
        dim3 g(NBP / 128, Bb / 128);          // 94 x 8
        k_mma<<<g, 256, MMA_SMEM>>>(p_Aq, p_Aq + Bb * 16, p_Sq, p_Uq,
                                    (long)Bb, (long)NB, out, u_b, 0);
    }
    k_sparse<<<Bb, 128>>>(olds, item_emb, out);
    k_omiga<<<(NB + 255) / 256, 256>>>(omiga, out + (size_t)Bb * NB + (size_t)NB * NB);
}

// round 11
// speedup vs baseline: 1.0924x; 1.0924x over previous
#include <cuda_runtime.h>
#include <cuda_bf16.h>
#include <math.h>
#include <stdint.h>

#define NB   12000
#define NBP  12032   // NB padded to 94*128
#define Dd   64
#define Bb   1024
#define Ll   20
#define BKk  10
#define NOLDn 20

// ---------------- scratch (device globals; no allocation allowed) ----------
__device__ float g_baskets[4 * Bb * Ll * Dd];
__device__ float g_s1[4 * Bb * Dd];
__device__ float g_s2[4 * Bb * Dd];
__device__ float g_s3[4 * Bb * Dd];
__device__ float g_lvec[4 * Bb * Dd];
__device__ float g_feach[4 * Bb * Dd];
__device__ float g_Afin[Bb * 128];              // [final | e_user]
__device__ float g_uwT[NBP * 64];               // u_w transposed: [e][k]
__device__ uint4 g_Sq[NBP * 16];                // e_all bf16 hi/lo fragments
__device__ uint4 g_Uq[NBP * 16];                // uwT fragments
__device__ uint4 g_Aq[2 * Bb * 16];             // Afin fragments (2 halves)

__device__ __forceinline__ float sigmoidf(float x) { return 1.f / (1.f + expf(-x)); }

// ===================== bf16x2 (split-2) mma.sync GEMM =======================
__device__ __forceinline__ void mma16(float* d, const uint32_t* a, const uint32_t* b) {
    asm volatile(
        "mma.sync.aligned.m16n8k16.row.col.f32.bf16.bf16.f32 "
        "{%0,%1,%2,%3}, {%4,%5,%6,%7}, {%8,%9}, {%0,%1,%2,%3};"
        : "+f"(d[0]), "+f"(d[1]), "+f"(d[2]), "+f"(d[3])
        : "r"(a[0]), "r"(a[1]), "r"(a[2]), "r"(a[3]), "r"(b[0]), "r"(b[1]));
}

__device__ __forceinline__ uint32_t packbf(__nv_bfloat16 lo, __nv_bfloat16 hi) {
    __nv_bfloat162 t = __halves2bfloat162(lo, hi);
    return *(uint32_t*)&t;
}

__device__ __forceinline__ void splitpair(float x, float y, uint32_t& hi, uint32_t& lo) {
    __nv_bfloat16 hx = __float2bfloat16_rn(x), hy = __float2bfloat16_rn(y);
    __nv_bfloat16 lx = __float2bfloat16_rn(x - __bfloat162float(hx));
    __nv_bfloat16 ly = __float2bfloat16_rn(y - __bfloat162float(hy));
    hi = packbf(hx, hy);
    lo = packbf(lx, ly);
}

// ---- prep: split a row-major fp32 matrix into fragment-layout uint4 array --
__global__ void k_prep(const float* __restrict__ src, long srows, int stride,
                       uint4* __restrict__ dst, long drows) {
    long gid = (long)blockIdx.x * blockDim.x + threadIdx.x;
    if (gid >= drows * 2) return;
    long row = gid >> 1;
    int h = (int)(gid & 1);          // k half: 0 -> k 0..31, 1 -> 32..63
    float f[32];
    if (row < srows) {
        const float* base = src + row * (long)stride + h * 32;
#pragma unroll
        for (int i = 0; i < 8; i++) *(float4*)&f[i * 4] = *(const float4*)&base[i * 4];
    } else {
#pragma unroll
        for (int i = 0; i < 32; i++) f[i] = 0.f;
    }
    uint4* d = dst + row * 16;
#pragma unroll
    for (int sb = 0; sb < 2; sb++) {
#pragma unroll
        for (int t = 0; t < 4; t++) {
            int k0 = sb * 16 + 2 * t;
            uint4 v;
            splitpair(f[k0], f[k0 + 1], v.x, v.z);
            splitpair(f[k0 + 8], f[k0 + 9], v.y, v.w);
            d[(2 * h + sb) * 4 + t] = v;
        }
    }
}

// Generic tile GEMM on pre-split fragment arrays. (R9 epilogue: staged, coalesced)
__global__ void __launch_bounds__(256, 2)
k_mma(const uint4* __restrict__ A1q, const uint4* __restrict__ A2q,
      const uint4* __restrict__ B1q, const uint4* __restrict__ B2q,
      long a_rows, long b_rows, float* __restrict__ C,
      const float* __restrict__ bias, int triangular)
{
    extern __shared__ float st[];    // 128*133 floats epilogue staging

    int tid = threadIdx.x;
    int bi, bj;
    if (triangular) {
        int lid = blockIdx.x;
        int r = (int)((sqrtf(8.f * (float)lid + 1.f) - 1.f) * 0.5f);
        while ((r + 1) * (r + 2) / 2 <= lid) r++;
        while (r * (r + 1) / 2 > lid) r--;
        bi = lid - r * (r + 1) / 2;
        bj = r;
    } else {
        bi = blockIdx.y; bj = blockIdx.x;
    }
    long i0 = (long)bi * 128, j0 = (long)bj * 128;

    int lane = tid & 31, wid = tid >> 5;
    int g = lane >> 2, tig = lane & 3;
    int wm = wid & 3, wn = wid >> 2;   // 4x2 warp grid -> 32x64 per warp

    float acc[2][8][4];
#pragma unroll
    for (int mt = 0; mt < 2; mt++)
#pragma unroll
        for (int nt = 0; nt < 8; nt++)
#pragma unroll
            for (int q = 0; q < 4; q++) acc[mt][nt][q] = 0.f;

    int arow0 = (int)i0 + wm * 32 + g;
    int bcol0 = (int)j0 + wn * 64 + g;

    int halves = (A2q != nullptr) ? 2 : 1;
    for (int h = 0; h < halves; h++) {
        const uint4* __restrict__ Aq = h ? A2q : A1q;
        const uint4* __restrict__ Bq = h ? B2q : B1q;
        const uint4* ap[2][2];
        const uint4* bp[8];
#pragma unroll
        for (int mt = 0; mt < 2; mt++) {
            int r0 = (arow0 + mt * 16) * 16 + tig;
            ap[mt][0] = Aq + r0;
            ap[mt][1] = Aq + r0 + 8 * 16;
        }
#pragma unroll
        for (int nt = 0; nt < 8; nt++)
            bp[nt] = Bq + (bcol0 + nt * 8) * 16 + tig;

#pragma unroll
        for (int s = 0; s < 4; s++) {
            uint32_t am[2][4], al[2][4];
#pragma unroll
            for (int mt = 0; mt < 2; mt++) {
                uint4 u0 = ap[mt][0][s * 4];
                uint4 u1 = ap[mt][1][s * 4];
                am[mt][0] = u0.x; am[mt][1] = u1.x; am[mt][2] = u0.y; am[mt][3] = u1.y;
                al[mt][0] = u0.z; al[mt][1] = u1.z; al[mt][2] = u0.w; al[mt][3] = u1.w;
            }
#pragma unroll
            for (int nt = 0; nt < 8; nt++) {
                uint4 u = bp[nt][s * 4];
                uint32_t bm[2] = { u.x, u.y };
                uint32_t bl[2] = { u.z, u.w };
#pragma unroll
                for (int mt = 0; mt < 2; mt++) {
                    float* a = acc[mt][nt];
                    mma16(a, am[mt], bm);
                    mma16(a, am[mt], bl);
                    mma16(a, al[mt], bm);
                }
            }
        }
    }

    // ---------------- epilogue: stage once, read direct + mirrored ----------
#pragma unroll
    for (int mt = 0; mt < 2; mt++)
#pragma unroll
        for (int nt = 0; nt < 8; nt++) {
            int R  = wm * 32 + mt * 16 + g;
            int Cc = wn * 64 + nt * 8 + 2 * tig;
            st[R * 133 + Cc]           = acc[mt][nt][0];
            st[R * 133 + Cc + 1]       = acc[mt][nt][1];
            st[(R + 8) * 133 + Cc]     = acc[mt][nt][2];
            st[(R + 8) * 133 + Cc + 1] = acc[mt][nt][3];
        }
    __syncthreads();

    {
        int cc = tid & 127, rb = tid >> 7;
        long gj = j0 + cc;
        float bv = 0.f;
        if (bias && gj < b_rows) bv = bias[gj];
#pragma unroll 8
        for (int q = 0; q < 64; q++) {
            int r = rb + 2 * q;
            long gi = i0 + r;
            if (gi < a_rows && gj < b_rows)
                C[gi * (long)NB + gj] = st[r * 133 + cc] + bv;
        }
    }

    if (triangular && bi != bj) {
        int ii = tid & 127, jb = tid >> 7;
        long gi = i0 + ii;
        if (gi < a_rows) {
#pragma unroll 8
            for (int q = 0; q < 64; q++) {
                int jj = jb + 2 * q;
                long gj = j0 + jj;
                if (gj < b_rows)
                    C[gj * (long)NB + gi] = st[ii * 133 + jj];
            }
        }
    }
}

// ---------------- u_w transpose: g_uwT[e][k] = u_w[k][e] --------------------
__global__ void __launch_bounds__(1024)
k_uwT(const float* __restrict__ u_w) {
    __shared__ float t[32][33];
    int e0 = blockIdx.x * 32, k0 = blockIdx.y * 32;
    int tx = threadIdx.x & 31, ty = threadIdx.x >> 5;
    t[ty][tx] = u_w[(long)(k0 + ty) * NB + e0 + tx];
    __syncthreads();
    g_uwT[(long)(e0 + ty) * 64 + k0 + tx] = t[tx][ty];
}

// 64-thread block reduction (broadcast result to all threads)
__device__ __forceinline__ float block64_reduce(float v, float* sbuf, int d) {
    sbuf[d] = v;
    __syncthreads();
    if (d < 32) {
        float r = sbuf[d] + sbuf[d + 32];
#pragma unroll
        for (int o = 16; o > 0; o >>= 1) r += __shfl_down_sync(0xffffffffu, r, o);
        if (d == 0) sbuf[0] = r;
    }
    __syncthreads();
    float r = sbuf[0];
    __syncthreads();
    return r;
}

// ---------------- kernel A: baskets gather-sum ------------------------------
__global__ void k_baskets(const int* __restrict__ click, const int* __restrict__ favor,
                          const int* __restrict__ cart, const int* __restrict__ buy,
                          const float* __restrict__ item_emb) {
    int t = threadIdx.x;
    int d = t & 63;
    int row = blockIdx.x * 4 + (t >> 6);
    int n = row / (Bb * Ll);
    int rem = row - n * (Bb * Ll);
    const int* idx;
    if (n == 0) idx = click; else if (n == 1) idx = favor;
    else if (n == 2) idx = cart; else idx = buy;
    idx += rem * BKk;
    float s = 0.f;
#pragma unroll
    for (int k = 0; k < BKk; k++) s += item_emb[idx[k] * Dd + d];
    g_baskets[row * Dd + d] = s;
}

// ---------------- kernel B: per-(n,b) attention + EMA + gate ----------------
__global__ void __launch_bounds__(64)
k_seq(const int* __restrict__ userData, const float* __restrict__ user_emb,
      const float* __restrict__ user_wd, const float* __restrict__ Wk,
      const float* __restrict__ bk, const float* __restrict__ gate_w,
      const float* __restrict__ gate_b, const float* __restrict__ alpha) {
    int nb = blockIdx.x;
    int n = nb / Bb, b = nb - n * Bb;
    int d = threadIdx.x;

    __shared__ float sb[Ll][Dd];
    __shared__ float sred[Dd];
    __shared__ float s_attn[Ll];

    const float* bas = g_baskets + (size_t)nb * Ll * Dd;
#pragma unroll
    for (int l = 0; l < Ll; l++) sb[l][d] = bas[l * Dd + d];

    float wkreg[Dd];
#pragma unroll
    for (int e = 0; e < Dd; e++) wkreg[e] = Wk[n * Dd * Dd + e * Dd + d];

    int u = userData[b];
    float eu = user_emb[u * Dd + d];
    float bkd = bk[n * Dd + d];
    __syncthreads();

    for (int l = 0; l < Ll; l++) {
        float kd = bkd;
#pragma unroll
        for (int e = 0; e < Dd; e++) kd += sb[l][e] * wkreg[e];
        kd = fmaxf(kd, 0.f);
        float sc = block64_reduce(eu * kd, sred, d);
        float rs = block64_reduce(sb[l][d], sred, d);
        if (d == 0) s_attn[l] = (rs != 0.f) ? sc * 0.125f : -1000000000.0f;
        __syncthreads();
    }

    float m = -3.4e38f;
#pragma unroll
    for (int l = 0; l < Ll; l++) m = fmaxf(m, s_attn[l]);
    float ex[Ll];
    float Z = 0.f;
#pragma unroll
    for (int l = 0; l < Ll; l++) { ex[l] = expf(s_attn[l] - m); Z += ex[l]; }
    float invZ = 1.f / Z;
    float lv = 0.f;
#pragma unroll
    for (int l = 0; l < Ll; l++) lv += ex[l] * invZ * sb[l][d];

    float w1 = sigmoidf(user_wd[u * 8 + 2 * n]);
    float w2 = sigmoidf(user_wd[u * 8 + 2 * n + 1]);
    float coef = 1.f - w2 * w1;
    float h1 = sb[0][d];
#pragma unroll
    for (int l = 1; l < Ll; l++) h1 = w1 * h1 + coef * sb[l][d];
    float h2 = sb[Ll / 2][d];
#pragma unroll
    for (int l = Ll / 2 + 1; l < Ll; l++) h2 = w1 * h2 + coef * sb[l][d];
    float h3 = w1 * sb[Ll - 2][d] + coef * sb[Ll - 1][d];

    float a0 = alpha[0], a1 = alpha[1];
    float fn = h1 + a0 * (h1 - h2) + a1 * (h1 - h3);

    float gsum = block64_reduce(fn * gate_w[d] + lv * gate_w[Dd + d], sred, d);
    float g = sigmoidf(gsum + gate_b[0]);
    float fe = g * fn + (1.f - g) * lv;

    int off = nb * Dd + d;
    g_s1[off] = h1; g_s2[off] = h2; g_s3[off] = h3;
    g_lvec[off] = lv; g_feach[off] = fe;
}

// ---------------- kernel C: mixture over behaviors --------------------------
__global__ void __launch_bounds__(64)
k_mix(const int* __restrict__ userData, const float* __restrict__ user_emb,
      const float* __restrict__ w_mix, const float* __restrict__ alpha,
      const float* __restrict__ gate_w, const float* __restrict__ gate_b) {
    int b = blockIdx.x;
    int d = threadIdx.x;
    __shared__ float sred[Dd];

    float w[4][4];
#pragma unroll
    for (int i = 0; i < 4; i++) {
        float mx = -3.4e38f;
#pragma unroll
        for (int j = 0; j < 4; j++) mx = fmaxf(mx, w_mix[i * 4 + j]);
        float Z = 0.f;
#pragma unroll
        for (int j = 0; j < 4; j++) { w[i][j] = expf(w_mix[i * 4 + j] - mx); Z += w[i][j]; }
        float inv = 1.f / Z;
#pragma unroll
        for (int j = 0; j < 4; j++) w[i][j] *= inv;
    }

    float s1m = 0.f, s2m = 0.f, s3m = 0.f, lm = 0.f;
#pragma unroll
    for (int n = 0; n < 4; n++) {
        int off = (n * Bb + b) * Dd + d;
        s1m += w[0][n] * g_s1[off];
        s2m += w[1][n] * g_s2[off];
        s3m += w[2][n] * g_s3[off];
        lm  += w[3][n] * g_lvec[off];
    }
    float a0 = alpha[0], a1 = alpha[1];
    float fin_ = s1m + a0 * (s1m - s2m) + a1 * (s1m - s3m);

    float gsum = block64_reduce(fin_ * gate_w[d] + lm * gate_w[Dd + d], sred, d);
    float gm = sigmoidf(gsum + gate_b[0]);
    float fin = gm * fin_ + (1.f - gm) * lm;

    g_Afin[b * 128 + d] = fin;
    g_Afin[b * 128 + Dd + d] = user_emb[userData[b] * Dd + d];
}

// ---------------- kernel G: sparse old-items corrections --------------------
__global__ void __launch_bounds__(128)
k_sparse(const int* __restrict__ oldItems, const float* __restrict__ item_emb,
         float* __restrict__ out) {
    int b = blockIdx.x;
    int t = threadIdx.x;
    int n = t >> 5, lane = t & 31;
    __shared__ int sh_old[4][NOLDn];
    __shared__ float sh_fin[Dd];
    if (t < Dd) sh_fin[t] = g_Afin[b * 128 + t];
    if (t < 4 * NOLDn) {
        int n2 = t / NOLDn, j = t - n2 * NOLDn;
        sh_old[n2][j] = oldItems[(n2 * Bb + b) * NOLDn + j];
    }
    __syncthreads();

    int d0 = lane, d1 = lane + 32;
    float diff0 = g_feach[(n * Bb + b) * Dd + d0] - sh_fin[d0];
    float diff1 = g_feach[(n * Bb + b) * Dd + d1] - sh_fin[d1];
    const float* eall = item_emb + Dd;

    for (int j = 0; j < NOLDn; j++) {
        int e = sh_old[n][j];
        bool dup = false;
        for (int j2 = 0; j2 < j; j2++) if (sh_old[n][j2] == e) dup = true;
        if (dup) continue;
        float v = diff0 * eall[e * Dd + d0] + diff1 * eall[e * Dd + d1];
#pragma unroll
        for (int o = 16; o > 0; o >>= 1) v += __shfl_down_sync(0xffffffffu, v, o);
        if (lane == 0) atomicAdd(&out[(size_t)b * NB + e], v);
    }
}

// ---------------- kernel F: omiga copy ---------------------------------------
__global__ void k_omiga(const float* __restrict__ omiga, float* __restrict__ out) {
    int i = blockIdx.x * blockDim.x + threadIdx.x;
    if (i < NB) out[i] = omiga[i + 1];
}

// ---------------- launch ------------------------------------------------------
extern "C" void kernel_launch(void* const* d_in, const int* in_sizes, int n_in,
                              void* d_out, int out_size) {
    const int* click = (const int*)d_in[0];
    const int* favor = (const int*)d_in[1];
    const int* cart  = (const int*)d_in[2];
    const int* buy   = (const int*)d_in[3];
    const int* user  = (const int*)d_in[4];
    const int* olds  = (const int*)d_in[5];
    const float* item_emb = (const float*)d_in[6];
    const float* user_emb = (const float*)d_in[7];
    const float* user_wd  = (const float*)d_in[8];
    const float* omiga    = (const float*)d_in[9];
    const float* w_mix    = (const float*)d_in[10];
    const float* alpha    = (const float*)d_in[11];
    const float* gate_w   = (const float*)d_in[12];
    const float* gate_b   = (const float*)d_in[13];
    const float* Wk       = (const float*)d_in[14];
    const float* bk       = (const float*)d_in[15];
    const float* u_w      = (const float*)d_in[16];
    const float* u_b      = (const float*)d_in[17];
    float* out = (float*)d_out;

    const int MMA_SMEM = 128 * 133 * 4;   // 68096 B epilogue staging
    cudaFuncSetAttribute(k_mma, cudaFuncAttributeMaxDynamicSharedMemorySize, MMA_SMEM);

    float *p_Afin, *p_uwT;
    uint4 *p_Sq, *p_Uq, *p_Aq;
    cudaGetSymbolAddress((void**)&p_Afin, g_Afin);
    cudaGetSymbolAddress((void**)&p_uwT,  g_uwT);
    cudaGetSymbolAddress((void**)&p_Sq,   g_Sq);
    cudaGetSymbolAddress((void**)&p_Uq,   g_Uq);
    cudaGetSymbolAddress((void**)&p_Aq,   g_Aq);

    const float* e_all = item_emb + Dd;   // rows 1..12000

    // one auxiliary stream + fork/join events, created once (first call =
    // correctness run). Work is identical on every call.
    static cudaStream_t s2 = []() {
        cudaStream_t s = nullptr;
        if (cudaStreamCreateWithFlags(&s, cudaStreamNonBlocking) != cudaSuccess) s = nullptr;
        return s;
    }();
    static cudaEvent_t evF = []() {
        cudaEvent_t e = nullptr;
        if (cudaEventCreateWithFlags(&e, cudaEventDisableTiming) != cudaSuccess) e = nullptr;
        return e;
    }();
    static cudaEvent_t evJ = []() {
        cudaEvent_t e = nullptr;
        if (cudaEventCreateWithFlags(&e, cudaEventDisableTiming) != cudaSuccess) e = nullptr;
        return e;
    }();
    bool par = (s2 != nullptr) && (evF != nullptr) && (evJ != nullptr);
    cudaStream_t gs = par ? s2 : (cudaStream_t)0;

    // prep Sq (needed by both sim and score) on main stream
    k_prep<<<(NBP * 2 + 255) / 256, 256>>>(e_all, (long)NB, 64, p_Sq, (long)NBP);

    // fork: sim runs on s2 concurrently with the prologue/score chain
    if (par) {
        cudaEventRecord(evF, 0);
        cudaStreamWaitEvent(s2, evF, 0);
    }
    {
        int nbT = NBP / 128;                  // 94
        k_mma<<<nbT * (nbT + 1) / 2, 256, MMA_SMEM, gs>>>(p_Sq, nullptr, p_Sq, nullptr,
                                                          (long)NB, (long)NB,
                                                          out + (size_t)Bb * NB, nullptr, 1);
    }

    // main-stream chain
    k_baskets<<<4 * Bb * Ll / 4, 256>>>(click, favor, cart, buy, item_emb);
    k_seq<<<4 * Bb, 64>>>(user, user_emb, user_wd, Wk, bk, gate_w, gate_b, alpha);
    k_mix<<<Bb, 64>>>(user, user_emb, w_mix, alpha, gate_w, gate_b);
    k_uwT<<<dim3(NB / 32, 2), 1024>>>(u_w);
    k_prep<<<(NBP * 2 + 255) / 256, 256>>>(p_uwT, (long)NB, 64, p_Uq, (long)NBP);
    k_prep<<<(Bb * 2 + 255) / 256, 256>>>(p_Afin, (long)Bb, 128, p_Aq, (long)Bb);
    k_prep<<<(Bb * 2 + 255) / 256, 256>>>(p_Afin + 64, (long)Bb, 128, p_Aq + Bb * 16, (long)Bb);

    // score = [final|e_user] @ [e_all^T ; u_w] + u_b  (two K=64 halves)
    {
        dim3 g(NBP / 128, Bb / 128);          // 94 x 8
        k_mma<<<g, 256, MMA_SMEM>>>(p_Aq, p_Aq + Bb * 16, p_Sq, p_Uq,
                                    (long)Bb, (long)NB, out, u_b, 0);
    }
    k_sparse<<<Bb, 128>>>(olds, item_emb, out);
    k_omiga<<<(NB + 255) / 256, 256>>>(omiga, out + (size_t)Bb * NB + (size_t)NB * NB);

    // join: main stream waits for sim before returning (capture validity)
    if (par) {
        cudaEventRecord(evJ, s2);
        cudaStreamWaitEvent(0, evJ, 0);
    }
}

// round 12
// speedup vs baseline: 1.1116x; 1.0176x over previous
#include <cuda_runtime.h>
#include <cuda_bf16.h>
#include <math.h>
#include <stdint.h>

#define NB   12000
#define NBP  12032   // NB padded to 94*128
#define Dd   64
#define Bb   1024
#define Ll   20
#define BKk  10
#define NOLDn 20
#define STR  132     // epilogue staging stride (divisible by 4)

// ---------------- scratch (device globals; no allocation allowed) ----------
__device__ float g_baskets[4 * Bb * Ll * Dd];
__device__ float g_s1[4 * Bb * Dd];
__device__ float g_s2[4 * Bb * Dd];
__device__ float g_s3[4 * Bb * Dd];
__device__ float g_lvec[4 * Bb * Dd];
__device__ float g_feach[4 * Bb * Dd];
__device__ float g_Afin[Bb * 128];              // [final | e_user]
__device__ float g_uwT[NBP * 64];               // u_w transposed: [e][k]
__device__ uint4 g_Sq[NBP * 16];                // e_all bf16 hi/lo fragments
__device__ uint4 g_Uq[NBP * 16];                // uwT fragments
__device__ uint4 g_Aq[2 * Bb * 16];             // Afin fragments (2 halves)

__device__ __forceinline__ float sigmoidf(float x) { return 1.f / (1.f + expf(-x)); }

// ===================== bf16x2 (split-2) mma.sync GEMM =======================
__device__ __forceinline__ void mma16(float* d, const uint32_t* a, const uint32_t* b) {
    asm volatile(
        "mma.sync.aligned.m16n8k16.row.col.f32.bf16.bf16.f32 "
        "{%0,%1,%2,%3}, {%4,%5,%6,%7}, {%8,%9}, {%0,%1,%2,%3};"
        : "+f"(d[0]), "+f"(d[1]), "+f"(d[2]), "+f"(d[3])
        : "r"(a[0]), "r"(a[1]), "r"(a[2]), "r"(a[3]), "r"(b[0]), "r"(b[1]));
}

__device__ __forceinline__ uint32_t packbf(__nv_bfloat16 lo, __nv_bfloat16 hi) {
    __nv_bfloat162 t = __halves2bfloat162(lo, hi);
    return *(uint32_t*)&t;
}

__device__ __forceinline__ void splitpair(float x, float y, uint32_t& hi, uint32_t& lo) {
    __nv_bfloat16 hx = __float2bfloat16_rn(x), hy = __float2bfloat16_rn(y);
    __nv_bfloat16 lx = __float2bfloat16_rn(x - __bfloat162float(hx));
    __nv_bfloat16 ly = __float2bfloat16_rn(y - __bfloat162float(hy));
    hi = packbf(hx, hy);
    lo = packbf(lx, ly);
}

// ---- prep: split a row-major fp32 matrix into fragment-layout uint4 array --
__global__ void k_prep(const float* __restrict__ src, long srows, int stride,
                       uint4* __restrict__ dst, long drows) {
    long gid = (long)blockIdx.x * blockDim.x + threadIdx.x;
    if (gid >= drows * 2) return;
    long row = gid >> 1;
    int h = (int)(gid & 1);
    float f[32];
    if (row < srows) {
        const float* base = src + row * (long)stride + h * 32;
#pragma unroll
        for (int i = 0; i < 8; i++) *(float4*)&f[i * 4] = *(const float4*)&base[i * 4];
    } else {
#pragma unroll
        for (int i = 0; i < 32; i++) f[i] = 0.f;
    }
    uint4* d = dst + row * 16;
#pragma unroll
    for (int sb = 0; sb < 2; sb++) {
#pragma unroll
        for (int t = 0; t < 4; t++) {
            int k0 = sb * 16 + 2 * t;
            uint4 v;
            splitpair(f[k0], f[k0 + 1], v.x, v.z);
            splitpair(f[k0 + 8], f[k0 + 9], v.y, v.w);
            d[(2 * h + sb) * 4 + t] = v;
        }
    }
}

// Generic tile GEMM on pre-split fragment arrays. Vectorized staged epilogue.
__global__ void __launch_bounds__(256, 2)
k_mma(const uint4* __restrict__ A1q, const uint4* __restrict__ A2q,
      const uint4* __restrict__ B1q, const uint4* __restrict__ B2q,
      long a_rows, long b_rows, float* __restrict__ C,
      const float* __restrict__ bias, int triangular)
{
    extern __shared__ float st[];    // 128*STR floats epilogue staging

    int tid = threadIdx.x;
    int bi, bj;
    if (triangular) {
        int lid = blockIdx.x;
        int r = (int)((sqrtf(8.f * (float)lid + 1.f) - 1.f) * 0.5f);
        while ((r + 1) * (r + 2) / 2 <= lid) r++;
        while (r * (r + 1) / 2 > lid) r--;
        bi = lid - r * (r + 1) / 2;
        bj = r;
    } else {
        bi = blockIdx.y; bj = blockIdx.x;
    }
    long i0 = (long)bi * 128, j0 = (long)bj * 128;

    int lane = tid & 31, wid = tid >> 5;
    int g = lane >> 2, tig = lane & 3;
    int wm = wid & 3, wn = wid >> 2;   // 4x2 warp grid -> 32x64 per warp

    float acc[2][8][4];
#pragma unroll
    for (int mt = 0; mt < 2; mt++)
#pragma unroll
        for (int nt = 0; nt < 8; nt++)
#pragma unroll
            for (int q = 0; q < 4; q++) acc[mt][nt][q] = 0.f;

    int arow0 = (int)i0 + wm * 32 + g;
    int bcol0 = (int)j0 + wn * 64 + g;

    int halves = (A2q != nullptr) ? 2 : 1;
    for (int h = 0; h < halves; h++) {
        const uint4* __restrict__ Aq = h ? A2q : A1q;
        const uint4* __restrict__ Bq = h ? B2q : B1q;
        const uint4* ap[2][2];
        const uint4* bp[8];
#pragma unroll
        for (int mt = 0; mt < 2; mt++) {
            int r0 = (arow0 + mt * 16) * 16 + tig;
            ap[mt][0] = Aq + r0;
            ap[mt][1] = Aq + r0 + 8 * 16;
        }
#pragma unroll
        for (int nt = 0; nt < 8; nt++)
            bp[nt] = Bq + (bcol0 + nt * 8) * 16 + tig;

#pragma unroll
        for (int s = 0; s < 4; s++) {
            uint32_t am[2][4], al[2][4];
#pragma unroll
            for (int mt = 0; mt < 2; mt++) {
                uint4 u0 = ap[mt][0][s * 4];
                uint4 u1 = ap[mt][1][s * 4];
                am[mt][0] = u0.x; am[mt][1] = u1.x; am[mt][2] = u0.y; am[mt][3] = u1.y;
                al[mt][0] = u0.z; al[mt][1] = u1.z; al[mt][2] = u0.w; al[mt][3] = u1.w;
            }
#pragma unroll
            for (int nt = 0; nt < 8; nt++) {
                uint4 u = bp[nt][s * 4];
                uint32_t bm[2] = { u.x, u.y };
                uint32_t bl[2] = { u.z, u.w };
#pragma unroll
                for (int mt = 0; mt < 2; mt++) {
                    float* a = acc[mt][nt];
                    mma16(a, am[mt], bm);
                    mma16(a, am[mt], bl);
                    mma16(a, al[mt], bm);
                }
            }
        }
    }

    bool interior = (i0 + 128 <= a_rows) && (j0 + 128 <= b_rows);
    int lane32 = tid & 31, w8 = tid >> 5;

    // ---------------- direct pass: stage row-major, vector read/write -------
#pragma unroll
    for (int mt = 0; mt < 2; mt++)
#pragma unroll
        for (int nt = 0; nt < 8; nt++) {
            int R  = wm * 32 + mt * 16 + g;
            int Cc = wn * 64 + nt * 8 + 2 * tig;
            st[R * STR + Cc]           = acc[mt][nt][0];
            st[R * STR + Cc + 1]       = acc[mt][nt][1];
            st[(R + 8) * STR + Cc]     = acc[mt][nt][2];
            st[(R + 8) * STR + Cc + 1] = acc[mt][nt][3];
        }
    __syncthreads();

    if (interior) {
        long gjb = j0 + lane32 * 4;
        float4 bb = make_float4(0.f, 0.f, 0.f, 0.f);
        if (bias) bb = *(const float4*)&bias[gjb];
#pragma unroll
        for (int q = 0; q < 16; q++) {
            int r = w8 + q * 8;
            float4 v = *(float4*)&st[r * STR + lane32 * 4];
            v.x += bb.x; v.y += bb.y; v.z += bb.z; v.w += bb.w;
            *(float4*)&C[(i0 + r) * (long)NB + gjb] = v;
        }
    } else {
        int cc = tid & 127, rb = tid >> 7;
        long gj = j0 + cc;
        float bv = 0.f;
        if (bias && gj < b_rows) bv = bias[gj];
#pragma unroll 8
        for (int q = 0; q < 64; q++) {
            int r = rb + 2 * q;
            long gi = i0 + r;
            if (gi < a_rows && gj < b_rows)
                C[gi * (long)NB + gj] = st[r * STR + cc] + bv;
        }
    }

    // ---------------- mirror pass (off-diag triangular): transposed stage ---
    if (triangular && bi != bj) {
        __syncthreads();   // direct reads done before overwrite
#pragma unroll
        for (int mt = 0; mt < 2; mt++)
#pragma unroll
            for (int nt = 0; nt < 8; nt++) {
                int R  = wm * 32 + mt * 16 + g;
                int Cc = wn * 64 + nt * 8 + 2 * tig;
                st[Cc * STR + R]           = acc[mt][nt][0];
                st[(Cc + 1) * STR + R]     = acc[mt][nt][1];
                st[Cc * STR + R + 8]       = acc[mt][nt][2];
                st[(Cc + 1) * STR + R + 8] = acc[mt][nt][3];
            }
        __syncthreads();
        // rows of transposed stage = jj; gi interior always (bi <= 92)
#pragma unroll
        for (int q = 0; q < 16; q++) {
            int jj = w8 + q * 8;
            long gj = j0 + jj;
            if (gj < b_rows) {
                float4 v = *(float4*)&st[jj * STR + lane32 * 4];
                *(float4*)&C[gj * (long)NB + i0 + lane32 * 4] = v;
            }
        }
    }
}

// ---------------- u_w transpose: g_uwT[e][k] = u_w[k][e] --------------------
__global__ void __launch_bounds__(1024)
k_uwT(const float* __restrict__ u_w) {
    __shared__ float t[32][33];
    int e0 = blockIdx.x * 32, k0 = blockIdx.y * 32;
    int tx = threadIdx.x & 31, ty = threadIdx.x >> 5;
    t[ty][tx] = u_w[(long)(k0 + ty) * NB + e0 + tx];
    __syncthreads();
    g_uwT[(long)(e0 + ty) * 64 + k0 + tx] = t[tx][ty];
}

// 64-thread block reduction (broadcast result to all threads)
__device__ __forceinline__ float block64_reduce(float v, float* sbuf, int d) {
    sbuf[d] = v;
    __syncthreads();
    if (d < 32) {
        float r = sbuf[d] + sbuf[d + 32];
#pragma unroll
        for (int o = 16; o > 0; o >>= 1) r += __shfl_down_sync(0xffffffffu, r, o);
        if (d == 0) sbuf[0] = r;
    }
    __syncthreads();
    float r = sbuf[0];
    __syncthreads();
    return r;
}

// ---------------- kernel A: baskets gather-sum ------------------------------
__global__ void k_baskets(const int* __restrict__ click, const int* __restrict__ favor,
                          const int* __restrict__ cart, const int* __restrict__ buy,
                          const float* __restrict__ item_emb) {
    int t = threadIdx.x;
    int d = t & 63;
    int row = blockIdx.x * 4 + (t >> 6);
    int n = row / (Bb * Ll);
    int rem = row - n * (Bb * Ll);
    const int* idx;
    if (n == 0) idx = click; else if (n == 1) idx = favor;
    else if (n == 2) idx = cart; else idx = buy;
    idx += rem * BKk;
    float s = 0.f;
#pragma unroll
    for (int k = 0; k < BKk; k++) s += item_emb[idx[k] * Dd + d];
    g_baskets[row * Dd + d] = s;
}

// ---------------- kernel B: per-(n,b) attention + EMA + gate ----------------
// Restructured: all 20 attention scores computed without per-l reductions.
__global__ void __launch_bounds__(64)
k_seq(const int* __restrict__ userData, const float* __restrict__ user_emb,
      const float* __restrict__ user_wd, const float* __restrict__ Wk,
      const float* __restrict__ bk, const float* __restrict__ gate_w,
      const float* __restrict__ gate_b, const float* __restrict__ alpha) {
    int nb = blockIdx.x;
    int n = nb / Bb, b = nb - n * Bb;
    int d = threadIdx.x;

    __shared__ float sb[Ll][66];     // padded: stride 66 (2d+e bank spread)
    __shared__ float sp[Ll][66];     // prod staging
    __shared__ float sred[Dd];
    __shared__ float s_attn[Ll];

    const float* bas = g_baskets + (size_t)nb * Ll * Dd;
#pragma unroll
    for (int l = 0; l < Ll; l++) sb[l][d] = bas[l * Dd + d];

    float wkreg[Dd];
#pragma unroll
    for (int e = 0; e < Dd; e++) wkreg[e] = Wk[n * Dd * Dd + e * Dd + d];

    int u = userData[b];
    float eu = user_emb[u * Dd + d];
    float bkd = bk[n * Dd + d];
    __syncthreads();

    // all 20 relu(k)·eu products, no synchronization
#pragma unroll
    for (int l = 0; l < Ll; l++) {
        float kd = bkd;
#pragma unroll
        for (int e = 0; e < Dd; e += 2) {
            float2 v = *(const float2*)&sb[l][e];
            kd += v.x * wkreg[e] + v.y * wkreg[e + 1];
        }
        sp[l][d] = eu * fmaxf(kd, 0.f);
    }
    __syncthreads();

    // 20 parallel reductions (thread d < 20 handles l = d)
    if (d < Ll) {
        float sc = 0.f, rs = 0.f;
#pragma unroll
        for (int e = 0; e < Dd; e++) { sc += sp[d][e]; rs += sb[d][e]; }
        s_attn[d] = (rs != 0.f) ? sc * 0.125f : -1000000000.0f;
    }
    __syncthreads();

    float m = -3.4e38f;
#pragma unroll
    for (int l = 0; l < Ll; l++) m = fmaxf(m, s_attn[l]);
    float ex[Ll];
    float Z = 0.f;
#pragma unroll
    for (int l = 0; l < Ll; l++) { ex[l] = expf(s_attn[l] - m); Z += ex[l]; }
    float invZ = 1.f / Z;
    float lv = 0.f;
#pragma unroll
    for (int l = 0; l < Ll; l++) lv += ex[l] * invZ * sb[l][d];

    float w1 = sigmoidf(user_wd[u * 8 + 2 * n]);
    float w2 = sigmoidf(user_wd[u * 8 + 2 * n + 1]);
    float coef = 1.f - w2 * w1;
    float h1 = sb[0][d];
#pragma unroll
    for (int l = 1; l < Ll; l++) h1 = w1 * h1 + coef * sb[l][d];
    float h2 = sb[Ll / 2][d];
#pragma unroll
    for (int l = Ll / 2 + 1; l < Ll; l++) h2 = w1 * h2 + coef * sb[l][d];
    float h3 = w1 * sb[Ll - 2][d] + coef * sb[Ll - 1][d];

    float a0 = alpha[0], a1 = alpha[1];
    float fn = h1 + a0 * (h1 - h2) + a1 * (h1 - h3);

    float gsum = block64_reduce(fn * gate_w[d] + lv * gate_w[Dd + d], sred, d);
    float g = sigmoidf(gsum + gate_b[0]);
    float fe = g * fn + (1.f - g) * lv;

    int off = nb * Dd + d;
    g_s1[off] = h1; g_s2[off] = h2; g_s3[off] = h3;
    g_lvec[off] = lv; g_feach[off] = fe;
}

// ---------------- kernel C: mixture over behaviors --------------------------
__global__ void __launch_bounds__(64)
k_mix(const int* __restrict__ userData, const float* __restrict__ user_emb,
      const float* __restrict__ w_mix, const float* __restrict__ alpha,
      const float* __restrict__ gate_w, const float* __restrict__ gate_b) {
    int b = blockIdx.x;
    int d = threadIdx.x;
    __shared__ float sred[Dd];

    float w[4][4];
#pragma unroll
    for (int i = 0; i < 4; i++) {
        float mx = -3.4e38f;
#pragma unroll
        for (int j = 0; j < 4; j++) mx = fmaxf(mx, w_mix[i * 4 + j]);
        float Z = 0.f;
#pragma unroll
        for (int j = 0; j < 4; j++) { w[i][j] = expf(w_mix[i * 4 + j] - mx); Z += w[i][j]; }
        float inv = 1.f / Z;
#pragma unroll
        for (int j = 0; j < 4; j++) w[i][j] *= inv;
    }

    float s1m = 0.f, s2m = 0.f, s3m = 0.f, lm = 0.f;
#pragma unroll
    for (int n = 0; n < 4; n++) {
        int off = (n * Bb + b) * Dd + d;
        s1m += w[0][n] * g_s1[off];
        s2m += w[1][n] * g_s2[off];
        s3m += w[2][n] * g_s3[off];
        lm  += w[3][n] * g_lvec[off];
    }
    float a0 = alpha[0], a1 = alpha[1];
    float fin_ = s1m + a0 * (s1m - s2m) + a1 * (s1m - s3m);

    float gsum = block64_reduce(fin_ * gate_w[d] + lm * gate_w[Dd + d], sred, d);
    float gm = sigmoidf(gsum + gate_b[0]);
    float fin = gm * fin_ + (1.f - gm) * lm;

    g_Afin[b * 128 + d] = fin;
    g_Afin[b * 128 + Dd + d] = user_emb[userData[b] * Dd + d];
}

// ---------------- kernel G: sparse old-items corrections --------------------
__global__ void __launch_bounds__(128)
k_sparse(const int* __restrict__ oldItems, const float* __restrict__ item_emb,
         float* __restrict__ out) {
    int b = blockIdx.x;
    int t = threadIdx.x;
    int n = t >> 5, lane = t & 31;
    __shared__ int sh_old[4][NOLDn];
    __shared__ float sh_fin[Dd];
    if (t < Dd) sh_fin[t] = g_Afin[b * 128 + t];
    if (t < 4 * NOLDn) {
        int n2 = t / NOLDn, j = t - n2 * NOLDn;
        sh_old[n2][j] = oldItems[(n2 * Bb + b) * NOLDn + j];
    }
    __syncthreads();

    int d0 = lane, d1 = lane + 32;
    float diff0 = g_feach[(n * Bb + b) * Dd + d0] - sh_fin[d0];
    float diff1 = g_feach[(n * Bb + b) * Dd + d1] - sh_fin[d1];
    const float* eall = item_emb + Dd;

    for (int j = 0; j < NOLDn; j++) {
        int e = sh_old[n][j];
        bool dup = false;
        for (int j2 = 0; j2 < j; j2++) if (sh_old[n][j2] == e) dup = true;
        if (dup) continue;
        float v = diff0 * eall[e * Dd + d0] + diff1 * eall[e * Dd + d1];
#pragma unroll
        for (int o = 16; o > 0; o >>= 1) v += __shfl_down_sync(0xffffffffu, v, o);
        if (lane == 0) atomicAdd(&out[(size_t)b * NB + e], v);
    }
}

// ---------------- kernel F: omiga copy ---------------------------------------
__global__ void k_omiga(const float* __restrict__ omiga, float* __restrict__ out) {
    int i = blockIdx.x * blockDim.x + threadIdx.x;
    if (i < NB) out[i] = omiga[i + 1];
}

// ---------------- launch ------------------------------------------------------
extern "C" void kernel_launch(void* const* d_in, const int* in_sizes, int n_in,
                              void* d_out, int out_size) {
    const int* click = (const int*)d_in[0];
    const int* favor = (const int*)d_in[1];
    const int* cart  = (const int*)d_in[2];
    const int* buy   = (const int*)d_in[3];
    const int* user  = (const int*)d_in[4];
    const int* olds  = (const int*)d_in[5];
    const float* item_emb = (const float*)d_in[6];
    const float* user_emb = (const float*)d_in[7];
    const float* user_wd  = (const float*)d_in[8];
    const float* omiga    = (const float*)d_in[9];
    const float* w_mix    = (const float*)d_in[10];
    const float* alpha    = (const float*)d_in[11];
    const float* gate_w   = (const float*)d_in[12];
    const float* gate_b   = (const float*)d_in[13];
    const float* Wk       = (const float*)d_in[14];
    const float* bk       = (const float*)d_in[15];
    const float* u_w      = (const float*)d_in[16];
    const float* u_b      = (const float*)d_in[17];
    float* out = (float*)d_out;

    const int MMA_SMEM = 128 * STR * 4;   // 67584 B epilogue staging
    cudaFuncSetAttribute(k_mma, cudaFuncAttributeMaxDynamicSharedMemorySize, MMA_SMEM);

    float *p_Afin, *p_uwT;
    uint4 *p_Sq, *p_Uq, *p_Aq;
    cudaGetSymbolAddress((void**)&p_Afin, g_Afin);
    cudaGetSymbolAddress((void**)&p_uwT,  g_uwT);
    cudaGetSymbolAddress((void**)&p_Sq,   g_Sq);
    cudaGetSymbolAddress((void**)&p_Uq,   g_Uq);
    cudaGetSymbolAddress((void**)&p_Aq,   g_Aq);

    const float* e_all = item_emb + Dd;   // rows 1..12000

    static cudaStream_t s2 = []() {
        cudaStream_t s = nullptr;
        if (cudaStreamCreateWithFlags(&s, cudaStreamNonBlocking) != cudaSuccess) s = nullptr;
        return s;
    }();
    static cudaEvent_t evF = []() {
        cudaEvent_t e = nullptr;
        if (cudaEventCreateWithFlags(&e, cudaEventDisableTiming) != cudaSuccess) e = nullptr;
        return e;
    }();
    static cudaEvent_t evJ = []() {
        cudaEvent_t e = nullptr;
        if (cudaEventCreateWithFlags(&e, cudaEventDisableTiming) != cudaSuccess) e = nullptr;
        return e;
    }();
    bool par = (s2 != nullptr) && (evF != nullptr) && (evJ != nullptr);
    cudaStream_t gs = par ? s2 : (cudaStream_t)0;

    // prep Sq (needed by both sim and score) on main stream
    k_prep<<<(NBP * 2 + 255) / 256, 256>>>(e_all, (long)NB, 64, p_Sq, (long)NBP);

    // fork: sim runs on s2 concurrently with the prologue/score chain
    if (par) {
        cudaEventRecord(evF, 0);
        cudaStreamWaitEvent(s2, evF, 0);
    }
    {
        int nbT = NBP / 128;                  // 94
        k_mma<<<nbT * (nbT + 1) / 2, 256, MMA_SMEM, gs>>>(p_Sq, nullptr, p_Sq, nullptr,
                                                          (long)NB, (long)NB,
                                                          out + (size_t)Bb * NB, nullptr, 1);
    }

    // main-stream chain
    k_baskets<<<4 * Bb * Ll / 4, 256>>>(click, favor, cart, buy, item_emb);
    k_seq<<<4 * Bb, 64>>>(user, user_emb, user_wd, Wk, bk, gate_w, gate_b, alpha);
    k_mix<<<Bb, 64>>>(user, user_emb, w_mix, alpha, gate_w, gate_b);
    k_uwT<<<dim3(NB / 32, 2), 1024>>>(u_w);
    k_prep<<<(NBP * 2 + 255) / 256, 256>>>(p_uwT, (long)NB, 64, p_Uq, (long)NBP);
    k_prep<<<(Bb * 2 + 255) / 256, 256>>>(p_Afin, (long)Bb, 128, p_Aq, (long)Bb);
    k_prep<<<(Bb * 2 + 255) / 256, 256>>>(p_Afin + 64, (long)Bb, 128, p_Aq + Bb * 16, (long)Bb);

    // score = [final|e_user] @ [e_all^T ; u_w] + u_b  (two K=64 halves)
    {
        dim3 g(NBP / 128, Bb / 128);          // 94 x 8
        k_mma<<<g, 256, MMA_SMEM>>>(p_Aq, p_Aq + Bb * 16, p_Sq, p_Uq,
                                    (long)Bb, (long)NB, out, u_b, 0);
    }
    k_sparse<<<Bb, 128>>>(olds, item_emb, out);
    k_omiga<<<(NB + 255) / 256, 256>>>(omiga, out + (size_t)Bb * NB + (size_t)NB * NB);

    // join: main stream waits for sim before returning (capture validity)
    if (par) {
        cudaEventRecord(evJ, s2);
        cudaStreamWaitEvent(0, evJ, 0);
    }
}

// round 14
// speedup vs baseline: 1.1194x; 1.0070x over previous
#include <cuda_runtime.h>
#include <cuda_bf16.h>
#include <math.h>
#include <stdint.h>

#define NB   12000
#define NBP  12032   // NB padded to 94*128
#define Dd   64
#define Bb   1024
#define Ll   20
#define BKk  10
#define NOLDn 20
#define STR  132     // epilogue staging stride (divisible by 4)

// ---------------- scratch (device globals; no allocation allowed) ----------
__device__ float g_baskets[4 * Bb * Ll * Dd];
__device__ float g_s1[4 * Bb * Dd];
__device__ float g_s2[4 * Bb * Dd];
__device__ float g_s3[4 * Bb * Dd];
__device__ float g_lvec[4 * Bb * Dd];
__device__ float g_feach[4 * Bb * Dd];
__device__ float g_Afin[Bb * 128];              // [final | e_user]
__device__ float g_uwT[NBP * 64];               // u_w transposed: [e][k]
__device__ uint4 g_Sq[NBP * 16];                // e_all bf16 hi/lo fragments
__device__ uint4 g_Uq[NBP * 16];                // uwT fragments
__device__ uint4 g_Aq[2 * Bb * 16];             // Afin fragments (2 halves)

__device__ __forceinline__ float sigmoidf(float x) { return 1.f / (1.f + expf(-x)); }

// ===================== bf16x2 (split-2) mma.sync GEMM =======================
__device__ __forceinline__ void mma16(float* d, const uint32_t* a, const uint32_t* b) {
    asm volatile(
        "mma.sync.aligned.m16n8k16.row.col.f32.bf16.bf16.f32 "
        "{%0,%1,%2,%3}, {%4,%5,%6,%7}, {%8,%9}, {%0,%1,%2,%3};"
        : "+f"(d[0]), "+f"(d[1]), "+f"(d[2]), "+f"(d[3])
        : "r"(a[0]), "r"(a[1]), "r"(a[2]), "r"(a[3]), "r"(b[0]), "r"(b[1]));
}

__device__ __forceinline__ uint32_t packbf(__nv_bfloat16 lo, __nv_bfloat16 hi) {
    __nv_bfloat162 t = __halves2bfloat162(lo, hi);
    return *(uint32_t*)&t;
}

__device__ __forceinline__ void splitpair(float x, float y, uint32_t& hi, uint32_t& lo) {
    __nv_bfloat16 hx = __float2bfloat16_rn(x), hy = __float2bfloat16_rn(y);
    __nv_bfloat16 lx = __float2bfloat16_rn(x - __bfloat162float(hx));
    __nv_bfloat16 ly = __float2bfloat16_rn(y - __bfloat162float(hy));
    hi = packbf(hx, hy);
    lo = packbf(lx, ly);
}

// ---- prep: split a row-major fp32 matrix into fragment-layout uint4 array --
__global__ void k_prep(const float* __restrict__ src, long srows, int stride,
                       uint4* __restrict__ dst, long drows) {
    long gid = (long)blockIdx.x * blockDim.x + threadIdx.x;
    if (gid >= drows * 2) return;
    long row = gid >> 1;
    int h = (int)(gid & 1);
    float f[32];
    if (row < srows) {
        const float* base = src + row * (long)stride + h * 32;
#pragma unroll
        for (int i = 0; i < 8; i++) *(float4*)&f[i * 4] = *(const float4*)&base[i * 4];
    } else {
#pragma unroll
        for (int i = 0; i < 32; i++) f[i] = 0.f;
    }
    uint4* d = dst + row * 16;
#pragma unroll
    for (int sb = 0; sb < 2; sb++) {
#pragma unroll
        for (int t = 0; t < 4; t++) {
            int k0 = sb * 16 + 2 * t;
            uint4 v;
            splitpair(f[k0], f[k0 + 1], v.x, v.z);
            splitpair(f[k0 + 8], f[k0 + 9], v.y, v.w);
            d[(2 * h + sb) * 4 + t] = v;
        }
    }
}

// Generic tile GEMM on pre-split fragment arrays. Vectorized staged epilogue.
__global__ void __launch_bounds__(256, 2)
k_mma(const uint4* __restrict__ A1q, const uint4* __restrict__ A2q,
      const uint4* __restrict__ B1q, const uint4* __restrict__ B2q,
      long a_rows, long b_rows, float* __restrict__ C,
      const float* __restrict__ bias, int triangular)
{
    extern __shared__ float st[];    // 128*STR floats epilogue staging

    int tid = threadIdx.x;
    int bi, bj;
    if (triangular) {
        int lid = blockIdx.x;
        int r = (int)((sqrtf(8.f * (float)lid + 1.f) - 1.f) * 0.5f);
        while ((r + 1) * (r + 2) / 2 <= lid) r++;
        while (r * (r + 1) / 2 > lid) r--;
        bi = lid - r * (r + 1) / 2;
        bj = r;
    } else {
        bi = blockIdx.y; bj = blockIdx.x;
    }
    long i0 = (long)bi * 128, j0 = (long)bj * 128;

    int lane = tid & 31, wid = tid >> 5;
    int g = lane >> 2, tig = lane & 3;
    int wm = wid & 3, wn = wid >> 2;   // 4x2 warp grid -> 32x64 per warp

    float acc[2][8][4];
#pragma unroll
    for (int mt = 0; mt < 2; mt++)
#pragma unroll
        for (int nt = 0; nt < 8; nt++)
#pragma unroll
            for (int q = 0; q < 4; q++) acc[mt][nt][q] = 0.f;

    int arow0 = (int)i0 + wm * 32 + g;
    int bcol0 = (int)j0 + wn * 64 + g;

    int halves = (A2q != nullptr) ? 2 : 1;
    for (int h = 0; h < halves; h++) {
        const uint4* __restrict__ Aq = h ? A2q : A1q;
        const uint4* __restrict__ Bq = h ? B2q : B1q;
        const uint4* ap[2][2];
        const uint4* bp[8];
#pragma unroll
        for (int mt = 0; mt < 2; mt++) {
            int r0 = (arow0 + mt * 16) * 16 + tig;
            ap[mt][0] = Aq + r0;
            ap[mt][1] = Aq + r0 + 8 * 16;
        }
#pragma unroll
        for (int nt = 0; nt < 8; nt++)
            bp[nt] = Bq + (bcol0 + nt * 8) * 16 + tig;

#pragma unroll
        for (int s = 0; s < 4; s++) {
            uint32_t am[2][4], al[2][4];
#pragma unroll
            for (int mt = 0; mt < 2; mt++) {
                uint4 u0 = ap[mt][0][s * 4];
                uint4 u1 = ap[mt][1][s * 4];
                am[mt][0] = u0.x; am[mt][1] = u1.x; am[mt][2] = u0.y; am[mt][3] = u1.y;
                al[mt][0] = u0.z; al[mt][1] = u1.z; al[mt][2] = u0.w; al[mt][3] = u1.w;
            }
#pragma unroll
            for (int nt = 0; nt < 8; nt++) {
                uint4 u = bp[nt][s * 4];
                uint32_t bm[2] = { u.x, u.y };
                uint32_t bl[2] = { u.z, u.w };
#pragma unroll
                for (int mt = 0; mt < 2; mt++) {
                    float* a = acc[mt][nt];
                    mma16(a, am[mt], bm);
                    mma16(a, am[mt], bl);
                    mma16(a, al[mt], bm);
                }
            }
        }
    }

    bool interior = (i0 + 128 <= a_rows) && (j0 + 128 <= b_rows);
    int lane32 = tid & 31, w8 = tid >> 5;

    // ---------------- direct pass: stage row-major (STS.64), vector rd/wr ---
#pragma unroll
    for (int mt = 0; mt < 2; mt++)
#pragma unroll
        for (int nt = 0; nt < 8; nt++) {
            int R  = wm * 32 + mt * 16 + g;
            int Cc = wn * 64 + nt * 8 + 2 * tig;
            *(float2*)&st[R * STR + Cc]       = make_float2(acc[mt][nt][0], acc[mt][nt][1]);
            *(float2*)&st[(R + 8) * STR + Cc] = make_float2(acc[mt][nt][2], acc[mt][nt][3]);
        }
    __syncthreads();

    if (interior) {
        long gjb = j0 + lane32 * 4;
        float4 bb = make_float4(0.f, 0.f, 0.f, 0.f);
        if (bias) bb = *(const float4*)&bias[gjb];
#pragma unroll
        for (int q = 0; q < 16; q++) {
            int r = w8 + q * 8;
            float4 v = *(float4*)&st[r * STR + lane32 * 4];
            v.x += bb.x; v.y += bb.y; v.z += bb.z; v.w += bb.w;
            *(float4*)&C[(i0 + r) * (long)NB + gjb] = v;
        }
    } else {
        int cc = tid & 127, rb = tid >> 7;
        long gj = j0 + cc;
        float bv = 0.f;
        if (bias && gj < b_rows) bv = bias[gj];
#pragma unroll 8
        for (int q = 0; q < 64; q++) {
            int r = rb + 2 * q;
            long gi = i0 + r;
            if (gi < a_rows && gj < b_rows)
                C[gi * (long)NB + gj] = st[r * STR + cc] + bv;
        }
    }

    // ---------------- mirror pass (off-diag triangular): transposed stage ---
    if (triangular && bi != bj) {
        __syncthreads();   // direct reads done before overwrite
#pragma unroll
        for (int mt = 0; mt < 2; mt++)
#pragma unroll
            for (int nt = 0; nt < 8; nt++) {
                int R  = wm * 32 + mt * 16 + g;
                int Cc = wn * 64 + nt * 8 + 2 * tig;
                st[Cc * STR + R]           = acc[mt][nt][0];
                st[(Cc + 1) * STR + R]     = acc[mt][nt][1];
                st[Cc * STR + R + 8]       = acc[mt][nt][2];
                st[(Cc + 1) * STR + R + 8] = acc[mt][nt][3];
            }
        __syncthreads();
#pragma unroll
        for (int q = 0; q < 16; q++) {
            int jj = w8 + q * 8;
            long gj = j0 + jj;
            if (gj < b_rows) {
                float4 v = *(float4*)&st[jj * STR + lane32 * 4];
                *(float4*)&C[gj * (long)NB + i0 + lane32 * 4] = v;
            }
        }
    }
}

// ---------------- u_w transpose: g_uwT[e][k] = u_w[k][e] --------------------
__global__ void __launch_bounds__(1024)
k_uwT(const float* __restrict__ u_w) {
    __shared__ float t[32][33];
    int e0 = blockIdx.x * 32, k0 = blockIdx.y * 32;
    int tx = threadIdx.x & 31, ty = threadIdx.x >> 5;
    t[ty][tx] = u_w[(long)(k0 + ty) * NB + e0 + tx];
    __syncthreads();
    g_uwT[(long)(e0 + ty) * 64 + k0 + tx] = t[tx][ty];
}

// 64-thread block reduction (broadcast result to all threads)
__device__ __forceinline__ float block64_reduce(float v, float* sbuf, int d) {
    sbuf[d] = v;
    __syncthreads();
    if (d < 32) {
        float r = sbuf[d] + sbuf[d + 32];
#pragma unroll
        for (int o = 16; o > 0; o >>= 1) r += __shfl_down_sync(0xffffffffu, r, o);
        if (d == 0) sbuf[0] = r;
    }
    __syncthreads();
    float r = sbuf[0];
    __syncthreads();
    return r;
}

// ---------------- kernel A: baskets gather-sum ------------------------------
__global__ void k_baskets(const int* __restrict__ click, const int* __restrict__ favor,
                          const int* __restrict__ cart, const int* __restrict__ buy,
                          const float* __restrict__ item_emb) {
    int t = threadIdx.x;
    int d = t & 63;
    int row = blockIdx.x * 4 + (t >> 6);
    int n = row / (Bb * Ll);
    int rem = row - n * (Bb * Ll);
    const int* idx;
    if (n == 0) idx = click; else if (n == 1) idx = favor;
    else if (n == 2) idx = cart; else idx = buy;
    idx += rem * BKk;
    float s = 0.f;
#pragma unroll
    for (int k = 0; k < BKk; k++) s += item_emb[idx[k] * Dd + d];
    g_baskets[row * Dd + d] = s;
}

// ---------------- kernel B: per-(n,b) attention + EMA + gate ----------------
__global__ void __launch_bounds__(64)
k_seq(const int* __restrict__ userData, const float* __restrict__ user_emb,
      const float* __restrict__ user_wd, const float* __restrict__ Wk,
      const float* __restrict__ bk, const float* __restrict__ gate_w,
      const float* __restrict__ gate_b, const float* __restrict__ alpha) {
    int nb = blockIdx.x;
    int n = nb / Bb, b = nb - n * Bb;
    int d = threadIdx.x;

    __shared__ float sb[Ll][68];     // stride 68: 16B-aligned rows (float4 LDS)
    __shared__ float spT[Dd][21];    // transposed products: spT[e][l]
    __shared__ float sred[Dd];
    __shared__ float s_attn[Ll];

    const float* bas = g_baskets + (size_t)nb * Ll * Dd;
#pragma unroll
    for (int l = 0; l < Ll; l++) sb[l][d] = bas[l * Dd + d];

    float wkreg[Dd];
#pragma unroll
    for (int e = 0; e < Dd; e++) wkreg[e] = Wk[n * Dd * Dd + e * Dd + d];

    int u = userData[b];
    float eu = user_emb[u * Dd + d];
    float bkd = bk[n * Dd + d];
    __syncthreads();

    // all 20 relu(k)·eu products, no synchronization; store transposed
#pragma unroll
    for (int l = 0; l < Ll; l++) {
        float kd = bkd;
#pragma unroll
        for (int e = 0; e < Dd; e += 4) {
            float4 v = *(const float4*)&sb[l][e];
            kd += v.x * wkreg[e] + v.y * wkreg[e + 1]
                + v.z * wkreg[e + 2] + v.w * wkreg[e + 3];
        }
        spT[d][l] = eu * fmaxf(kd, 0.f);
    }
    __syncthreads();

    // 20 parallel reductions (thread d < 20 handles l = d)
    if (d < Ll) {
        float sc = 0.f, rs = 0.f;
#pragma unroll
        for (int e = 0; e < Dd; e++) { sc += spT[e][d]; rs += sb[d][e]; }
        s_attn[d] = (rs != 0.f) ? sc * 0.125f : -1000000000.0f;
    }
    __syncthreads();

    float m = -3.4e38f;
#pragma unroll
    for (int l = 0; l < Ll; l++) m = fmaxf(m, s_attn[l]);
    float ex[Ll];
    float Z = 0.f;
#pragma unroll
    for (int l = 0; l < Ll; l++) { ex[l] = expf(s_attn[l] - m); Z += ex[l]; }
    float invZ = 1.f / Z;
    float lv = 0.f;
#pragma unroll
    for (int l = 0; l < Ll; l++) lv += ex[l] * invZ * sb[l][d];

    float w1 = sigmoidf(user_wd[u * 8 + 2 * n]);
    float w2 = sigmoidf(user_wd[u * 8 + 2 * n + 1]);
    float coef = 1.f - w2 * w1;
    float h1 = sb[0][d];
#pragma unroll
    for (int l = 1; l < Ll; l++) h1 = w1 * h1 + coef * sb[l][d];
    float h2 = sb[Ll / 2][d];
#pragma unroll
    for (int l = Ll / 2 + 1; l < Ll; l++) h2 = w1 * h2 + coef * sb[l][d];
    float h3 = w1 * sb[Ll - 2][d] + coef * sb[Ll - 1][d];

    float a0 = alpha[0], a1 = alpha[1];
    float fn = h1 + a0 * (h1 - h2) + a1 * (h1 - h3);

    float gsum = block64_reduce(fn * gate_w[d] + lv * gate_w[Dd + d], sred, d);
    float g = sigmoidf(gsum + gate_b[0]);
    float fe = g * fn + (1.f - g) * lv;

    int off = nb * Dd + d;
    g_s1[off] = h1; g_s2[off] = h2; g_s3[off] = h3;
    g_lvec[off] = lv; g_feach[off] = fe;
}

// ---------------- kernel C: mixture over behaviors --------------------------
__global__ void __launch_bounds__(64)
k_mix(const int* __restrict__ userData, const float* __restrict__ user_emb,
      const float* __restrict__ w_mix, const float* __restrict__ alpha,
      const float* __restrict__ gate_w, const float* __restrict__ gate_b) {
    int b = blockIdx.x;
    int d = threadIdx.x;
    __shared__ float sred[Dd];

    float w[4][4];
#pragma unroll
    for (int i = 0; i < 4; i++) {
        float mx = -3.4e38f;
#pragma unroll
        for (int j = 0; j < 4; j++) mx = fmaxf(mx, w_mix[i * 4 + j]);
        float Z = 0.f;
#pragma unroll
        for (int j = 0; j < 4; j++) { w[i][j] = expf(w_mix[i * 4 + j] - mx); Z += w[i][j]; }
        float inv = 1.f / Z;
#pragma unroll
        for (int j = 0; j < 4; j++) w[i][j] *= inv;
    }

    float s1m = 0.f, s2m = 0.f, s3m = 0.f, lm = 0.f;
#pragma unroll
    for (int n = 0; n < 4; n++) {
        int off = (n * Bb + b) * Dd + d;
        s1m += w[0][n] * g_s1[off];
        s2m += w[1][n] * g_s2[off];
        s3m += w[2][n] * g_s3[off];
        lm  += w[3][n] * g_lvec[off];
    }
    float a0 = alpha[0], a1 = alpha[1];
    float fin_ = s1m + a0 * (s1m - s2m) + a1 * (s1m - s3m);

    float gsum = block64_reduce(fin_ * gate_w[d] + lm * gate_w[Dd + d], sred, d);
    float gm = sigmoidf(gsum + gate_b[0]);
    float fin = gm * fin_ + (1.f - gm) * lm;

    g_Afin[b * 128 + d] = fin;
    g_Afin[b * 128 + Dd + d] = user_emb[userData[b] * Dd + d];
}

// ---------------- kernel G: sparse old-items corrections --------------------
__global__ void __launch_bounds__(128)
k_sparse(const int* __restrict__ oldItems, const float* __restrict__ item_emb,
         float* __restrict__ out) {
    int b = blockIdx.x;
    int t = threadIdx.x;
    int n = t >> 5, lane = t & 31;
    __shared__ int sh_old[4][NOLDn];
    __shared__ float sh_fin[Dd];
    if (t < Dd) sh_fin[t] = g_Afin[b * 128 + t];
    if (t < 4 * NOLDn) {
        int n2 = t / NOLDn, j = t - n2 * NOLDn;
        sh_old[n2][j] = oldItems[(n2 * Bb + b) * NOLDn + j];
    }
    __syncthreads();

    int d0 = lane, d1 = lane + 32;
    float diff0 = g_feach[(n * Bb + b) * Dd + d0] - sh_fin[d0];
    float diff1 = g_feach[(n * Bb + b) * Dd + d1] - sh_fin[d1];
    const float* eall = item_emb + Dd;

    for (int j = 0; j < NOLDn; j++) {
        int e = sh_old[n][j];
        bool dup = false;
        for (int j2 = 0; j2 < j; j2++) if (sh_old[n][j2] == e) dup = true;
        if (dup) continue;
        float v = diff0 * eall[e * Dd + d0] + diff1 * eall[e * Dd + d1];
#pragma unroll
        for (int o = 16; o > 0; o >>= 1) v += __shfl_down_sync(0xffffffffu, v, o);
        if (lane == 0) atomicAdd(&out[(size_t)b * NB + e], v);
    }
}

// ---------------- kernel F: omiga copy ---------------------------------------
__global__ void k_omiga(const float* __restrict__ omiga, float* __restrict__ out) {
    int i = blockIdx.x * blockDim.x + threadIdx.x;
    if (i < NB) out[i] = omiga[i + 1];
}

// ---------------- launch ------------------------------------------------------
extern "C" void kernel_launch(void* const* d_in, const int* in_sizes, int n_in,
                              void* d_out, int out_size) {
    const int* click = (const int*)d_in[0];
    const int* favor = (const int*)d_in[1];
    const int* cart  = (const int*)d_in[2];
    const int* buy   = (const int*)d_in[3];
    const int* user  = (const int*)d_in[4];
    const int* olds  = (const int*)d_in[5];
    const float* item_emb = (const float*)d_in[6];
    const float* user_emb = (const float*)d_in[7];
    const float* user_wd  = (const float*)d_in[8];
    const float* omiga    = (const float*)d_in[9];
    const float* w_mix    = (const float*)d_in[10];
    const float* alpha    = (const float*)d_in[11];
    const float* gate_w   = (const float*)d_in[12];
    const float* gate_b   = (const float*)d_in[13];
    const float* Wk       = (const float*)d_in[14];
    const float* bk       = (const float*)d_in[15];
    const float* u_w      = (const float*)d_in[16];
    const float* u_b      = (const float*)d_in[17];
    float* out = (float*)d_out;

    const int MMA_SMEM = 128 * STR * 4;   // 67584 B epilogue staging
    cudaFuncSetAttribute(k_mma, cudaFuncAttributeMaxDynamicSharedMemorySize, MMA_SMEM);

    float *p_Afin, *p_uwT;
    uint4 *p_Sq, *p_Uq, *p_Aq;
    cudaGetSymbolAddress((void**)&p_Afin, g_Afin);
    cudaGetSymbolAddress((void**)&p_uwT,  g_uwT);
    cudaGetSymbolAddress((void**)&p_Sq,   g_Sq);
    cudaGetSymbolAddress((void**)&p_Uq,   g_Uq);
    cudaGetSymbolAddress((void**)&p_Aq,   g_Aq);

    const float* e_all = item_emb + Dd;   // rows 1..12000

    static cudaStream_t s2 = []() {
        cudaStream_t s = nullptr;
        if (cudaStreamCreateWithFlags(&s, cudaStreamNonBlocking) != cudaSuccess) s = nullptr;
        return s;
    }();
    static cudaEvent_t evF = []() {
        cudaEvent_t e = nullptr;
        if (cudaEventCreateWithFlags(&e, cudaEventDisableTiming) != cudaSuccess) e = nullptr;
        return e;
    }();
    static cudaEvent_t evJ = []() {
        cudaEvent_t e = nullptr;
        if (cudaEventCreateWithFlags(&e, cudaEventDisableTiming) != cudaSuccess) e = nullptr;
        return e;
    }();
    bool par = (s2 != nullptr) && (evF != nullptr) && (evJ != nullptr);
    cudaStream_t gs = par ? s2 : (cudaStream_t)0;

    // prep Sq (needed by both sim and score) on main stream
    k_prep<<<(NBP * 2 + 255) / 256, 256>>>(e_all, (long)NB, 64, p_Sq, (long)NBP);

    // fork: sim runs on s2 concurrently with the prologue/score chain
    if (par) {
        cudaEventRecord(evF, 0);
        cudaStreamWaitEvent(s2, evF, 0);
    }
    {
        int nbT = NBP / 128;                  // 94
        k_mma<<<nbT * (nbT + 1) / 2, 256, MMA_SMEM, gs>>>(p_Sq, nullptr, p_Sq, nullptr,
                                                          (long)NB, (long)NB,
                                                          out + (size_t)Bb * NB, nullptr, 1);
    }

    // main-stream chain
    k_baskets<<<4 * Bb * Ll / 4, 256>>>(click, favor, cart, buy, item_emb);
    k_seq<<<4 * Bb, 64>>>(user, user_emb, user_wd, Wk, bk, gate_w, gate_b, alpha);
    k_mix<<<Bb, 64>>>(user, user_emb, w_mix, alpha, gate_w, gate_b);
    k_uwT<<<dim3(NB / 32, 2), 1024>>>(u_w);
    k_prep<<<(NBP * 2 + 255) / 256, 256>>>(p_uwT, (long)NB, 64, p_Uq, (long)NBP);
    k_prep<<<(Bb * 2 + 255) / 256, 256>>>(p_Afin, (long)Bb, 128, p_Aq, (long)Bb);
    k_prep<<<(Bb * 2 + 255) / 256, 256>>>(p_Afin + 64, (long)Bb, 128, p_Aq + Bb * 16, (long)Bb);

    // score = [final|e_user] @ [e_all^T ; u_w] + u_b  (two K=64 halves)
    {
        dim3 g(NBP / 128, Bb / 128);          // 94 x 8
        k_mma<<<g, 256, MMA_SMEM>>>(p_Aq, p_Aq + Bb * 16, p_Sq, p_Uq,
                                    (long)Bb, (long)NB, out, u_b, 0);
    }
    k_sparse<<<Bb, 128>>>(olds, item_emb, out);
    k_omiga<<<(NB + 255) / 256, 256>>>(omiga, out + (size_t)Bb * NB + (size_t)NB * NB);

    // join: main stream waits for sim before returning (capture validity)
    if (par) {
        cudaEventRecord(evJ, s2);
        cudaStreamWaitEvent(0, evJ, 0);
    }
}